// round 10
// baseline (speedup 1.0000x reference)
#include <cuda_runtime.h>
#include <cuda_fp16.h>
#include <mma.h>
#include <math.h>

using namespace nvcuda;

#define T_ 6
#define N_ 20000
#define E_ 400000
#define F_ 64
#define C_ 64
#define H_ 128
#define BIG_ 0x3fffffff
#define NW_ ((N_ + 31) / 32)   // 625 mask words per snapshot

// ---------------- scratch (device globals; no allocation) ----------------
__device__ __align__(128) unsigned g_mA[T_][NW_];   // centers
__device__ __align__(128) unsigned g_mB[T_][NW_];   // after hop 1 (includes A)
__device__ __align__(128) unsigned g_mC[T_][NW_];   // hop-2 delta
__device__ __align__(128) int    g_count[T_][N_];
__device__ __align__(128) int    g_rowptr[T_][N_ + 1];
__device__ __align__(128) int    g_cursor[T_][N_];
__device__ __align__(128) int    g_csrsrc[T_][E_];
__device__ __align__(128) float  g_dinv[T_][N_];
__device__ __align__(128) __half g_xh[T_][N_ * F_];   // half copy of x
__device__ __align__(128) __half g_w1h[F_ * H_];      // half copy of W1[0:64]
__device__ __align__(128) __half g_g1[T_][N_ * H_];   // g1 = dinv*(xl@W1), fp16
__device__ __align__(128) __half g_colh[T_][N_];      // dinv*(h1 . W2[:,127]), fp16
__device__ unsigned long long    g_argmax[T_];
__device__ __align__(128) float  g_seq[T_ * H_];

// ---------------- init: masks + seeds + count zero + argmax ----------------
__global__ void k_init(const int* __restrict__ tgt) {
    int t = blockIdx.y;
    if (blockIdx.x == 0) {
        for (int w = threadIdx.x; w < NW_; w += 256) {
            g_mA[t][w] = 0u; g_mB[t][w] = 0u; g_mC[t][w] = 0u;
        }
        __syncthreads();
        if (threadIdx.x < C_) {
            int n = tgt[t * C_ + threadIdx.x];
            atomicOr(&g_mA[t][n >> 5], 1u << (n & 31));
            atomicOr(&g_mB[t][n >> 5], 1u << (n & 31));
        }
        if (threadIdx.x == 0) g_argmax[t] = 0ULL;
    } else {
        for (int i = (blockIdx.x - 1) * 256 + threadIdx.x; i < N_; i += (gridDim.x - 1) * 256)
            g_count[t][i] = 0;
    }
}

// ---------------- BFS hop 1: read A, write B (B pre-init = A) ----------------
__global__ void k_prop1(const int* __restrict__ ei) {
    int t = blockIdx.y;
    int i = blockIdx.x * blockDim.x + threadIdx.x;
    if (i >= E_) return;
    const int* src = ei + (size_t)t * 2 * E_;
    const int* dst = src + E_;
    int s = src[i], d = dst[i];
    unsigned inS = (g_mA[t][s >> 5] >> (s & 31)) & 1u;
    unsigned inD = (g_mA[t][d >> 5] >> (d & 31)) & 1u;
    if (inS && !inD) {
        if (!((g_mB[t][d >> 5] >> (d & 31)) & 1u))
            atomicOr(&g_mB[t][d >> 5], 1u << (d & 31));
    }
    if (inD && !inS) {
        if (!((g_mB[t][s >> 5] >> (s & 31)) & 1u))
            atomicOr(&g_mB[t][s >> 5], 1u << (s & 31));
    }
}

// ---------------- BFS hop 2: read B, write C (delta; final in = B|C) ----------------
__global__ void k_prop2(const int* __restrict__ ei) {
    int t = blockIdx.y;
    int i = blockIdx.x * blockDim.x + threadIdx.x;
    if (i >= E_) return;
    const int* src = ei + (size_t)t * 2 * E_;
    const int* dst = src + E_;
    int s = src[i], d = dst[i];
    unsigned inS = (g_mB[t][s >> 5] >> (s & 31)) & 1u;
    unsigned inD = (g_mB[t][d >> 5] >> (d & 31)) & 1u;
    if (inS && !inD) {
        if (!((g_mC[t][d >> 5] >> (d & 31)) & 1u))
            atomicOr(&g_mC[t][d >> 5], 1u << (d & 31));
    }
    if (inD && !inS) {
        if (!((g_mC[t][s >> 5] >> (s & 31)) & 1u))
            atomicOr(&g_mC[t][s >> 5], 1u << (s & 31));
    }
}

// ---------------- half conversions (fork branch) ----------------
__global__ void k_xhalf(const float* __restrict__ x) {
    int t = blockIdx.y;
    int i4 = (blockIdx.x * 256 + threadIdx.x) * 4;
    if (i4 >= N_ * F_) return;
    float4 v = *(const float4*)&x[(size_t)t * N_ * F_ + i4];
    __half2 p0 = __floats2half2_rn(v.x, v.y);
    __half2 p1 = __floats2half2_rn(v.z, v.w);
    *(uint2*)&g_xh[t][i4] = make_uint2(*(unsigned*)&p0, *(unsigned*)&p1);
}

__global__ void k_w1half(const float* __restrict__ W1) {
    for (int i = threadIdx.x * 2; i < F_ * H_; i += 512) {
        __half2 p = __floats2half2_rn(W1[i], W1[i + 1]);
        *(unsigned*)&g_w1h[i] = *(unsigned*)&p;
    }
}

// ---------------- CSR branch (FULL graph; no BFS dependence) ----------------
__global__ void k_count(const int* __restrict__ ei) {
    int t = blockIdx.y;
    int i = blockIdx.x * blockDim.x + threadIdx.x;
    if (i >= E_) return;
    const int* dst = ei + (size_t)t * 2 * E_ + E_;
    atomicAdd(&g_count[t][dst[i]], 1);
}

__global__ void k_scan() {
    int t = blockIdx.x;
    const int CH = 20;
    __shared__ int s[1024];
    int tid = threadIdx.x;
    int base = tid * CH;
    int loc[CH];
    int sum = 0;
#pragma unroll
    for (int i = 0; i < CH; i++) {
        int idx = base + i;
        int c = (idx < N_) ? g_count[t][idx] : 0;
        loc[i] = sum;
        sum += c;
    }
    s[tid] = sum;
    __syncthreads();
    for (int off = 1; off < 1024; off <<= 1) {
        int v = (tid >= off) ? s[tid - off] : 0;
        __syncthreads();
        s[tid] += v;
        __syncthreads();
    }
    int excl = s[tid] - sum;
#pragma unroll
    for (int i = 0; i < CH; i++) {
        int idx = base + i;
        if (idx < N_) {
            int o = excl + loc[i];
            g_rowptr[t][idx] = o;
            g_cursor[t][idx] = o;
        }
    }
    if (tid == 1023) g_rowptr[t][N_] = s[1023];
}

__global__ void k_fill(const int* __restrict__ ei) {
    int t = blockIdx.y;
    int i = blockIdx.x * blockDim.x + threadIdx.x;
    if (i >= E_) return;
    const int* src = ei + (size_t)t * 2 * E_;
    const int* dst = src + E_;
    int s = src[i], d = dst[i];
    int p = atomicAdd(&g_cursor[t][d], 1);
    g_csrsrc[t][p] = s;
}

__device__ __forceinline__ float warp_sum(float v) {
    v += __shfl_down_sync(0xffffffffu, v, 16);
    v += __shfl_down_sync(0xffffffffu, v, 8);
    v += __shfl_down_sync(0xffffffffu, v, 4);
    v += __shfl_down_sync(0xffffffffu, v, 2);
    v += __shfl_down_sync(0xffffffffu, v, 1);
    return v;
}
__device__ __forceinline__ int warp_sumi(int v) {
    v += __shfl_down_sync(0xffffffffu, v, 16);
    v += __shfl_down_sync(0xffffffffu, v, 8);
    v += __shfl_down_sync(0xffffffffu, v, 4);
    v += __shfl_down_sync(0xffffffffu, v, 2);
    v += __shfl_down_sync(0xffffffffu, v, 1);
    return v;
}

// ---------------- tensor-core GEMM with fused deg/dinv/label prologue ------------
// g1(half) = dinv * ([x,labels] @ W1); also writes g_dinv.
#define BM2 128
#define A_LDM 72
#define STG_LDM 136
__global__ void __launch_bounds__(256) k_gemm(const float* __restrict__ W1) {
    extern __shared__ char smraw[];
    __half* Axs = (__half*)smraw;                       // [128][72]
    __half* W1s = (__half*)(smraw + BM2 * A_LDM * 2);   // [64][128]
    float* stg = (float*)smraw;                         // [4][16][136] (phase 2)
    __shared__ float sdinv[BM2];
    __shared__ unsigned char slab[BM2];

    int t = blockIdx.y;
    int tid = threadIdx.x;
    int warp = tid >> 5, lane = tid & 31;
    int m0 = blockIdx.x * BM2;
    const __half* __restrict__ xh = g_xh[t];

    // prologue: subgraph degree -> dinv, labels (masks are L1-resident)
    const unsigned* __restrict__ mA = g_mA[t];
    const unsigned* __restrict__ mB = g_mB[t];
    const unsigned* __restrict__ mC = g_mC[t];
    const int* __restrict__ csr = g_csrsrc[t];
    for (int rr = 0; rr < 16; rr++) {
        int r = warp * 16 + rr;
        int row = m0 + r;
        int cnt = 0;
        bool in = false, cen = false;
        if (row < N_) {
            unsigned wIn = mB[row >> 5] | mC[row >> 5];
            in = (wIn >> (row & 31)) & 1u;
            cen = (mA[row >> 5] >> (row & 31)) & 1u;
            if (in) {
                int s0 = g_rowptr[t][row], s1 = g_rowptr[t][row + 1];
                for (int j = s0 + lane; j < s1; j += 32) {
                    int u = csr[j];
                    cnt += (int)(((mB[u >> 5] | mC[u >> 5]) >> (u & 31)) & 1u);
                }
            }
        }
        cnt = warp_sumi(cnt);
        if (lane == 0) {
            float dv = in ? rsqrtf((float)cnt + 1.0f) : 0.0f;
            sdinv[r] = dv;
            slab[r] = cen ? 1 : (in ? 2 : 0);
            if (row < N_) g_dinv[t][row] = dv;
        }
    }

    // load A tile: 128 rows x 64 halfs = 1024 uint4
#pragma unroll
    for (int i = 0; i < 4; i++) {
        int e = tid + i * 256;
        int r = e >> 3, q = e & 7;
        int gr = m0 + r;
        uint4 v = make_uint4(0, 0, 0, 0);
        if (gr < N_) v = *(const uint4*)&xh[(size_t)gr * F_ + q * 8];
        *(uint4*)&Axs[r * A_LDM + q * 8] = v;
    }
    // load W tile: 64 x 128 halfs
#pragma unroll
    for (int i = 0; i < 4; i++) {
        int e = tid + i * 256;
        int r = e >> 4, q = e & 15;
        *(uint4*)&W1s[r * H_ + q * 8] = *(const uint4*)&g_w1h[r * H_ + q * 8];
    }
    __syncthreads();

    wmma::fragment<wmma::accumulator, 16, 16, 16, float> acc[8];
#pragma unroll
    for (int nt = 0; nt < 8; nt++) wmma::fill_fragment(acc[nt], 0.0f);

#pragma unroll
    for (int ks = 0; ks < 4; ks++) {
        wmma::fragment<wmma::matrix_a, 16, 16, 16, __half, wmma::row_major> af;
        wmma::load_matrix_sync(af, Axs + warp * 16 * A_LDM + ks * 16, A_LDM);
#pragma unroll
        for (int nt = 0; nt < 8; nt++) {
            wmma::fragment<wmma::matrix_b, 16, 16, 16, __half, wmma::row_major> bf;
            wmma::load_matrix_sync(bf, W1s + ks * 16 * H_ + nt * 16, H_);
            wmma::mma_sync(acc[nt], af, bf, acc[nt]);
        }
    }
    __syncthreads();  // tiles dead; smem becomes staging

    float w64[4], w65[4];
#pragma unroll
    for (int j = 0; j < 4; j++) {
        w64[j] = W1[(size_t)64 * H_ + lane * 4 + j];
        w65[j] = W1[(size_t)65 * H_ + lane * 4 + j];
    }

#pragma unroll
    for (int grp = 0; grp < 2; grp++) {
        bool mine = (warp >> 2) == grp;
        int wslot = warp & 3;
        if (mine) {
#pragma unroll
            for (int nt = 0; nt < 8; nt++)
                wmma::store_matrix_sync(stg + wslot * 16 * STG_LDM + nt * 16, acc[nt],
                                        STG_LDM, wmma::mem_row_major);
        }
        __syncthreads();
        if (mine) {
            for (int r = 0; r < 16; r++) {
                int gr = m0 + warp * 16 + r;
                if (gr >= N_) break;
                int lb = slab[warp * 16 + r];
                float l0 = (lb == 1) ? 1.0f : 0.0f;
                float l1 = (lb == 2) ? 1.0f : 0.0f;
                float d = sdinv[warp * 16 + r];
                const float* srow = stg + wslot * 16 * STG_LDM + r * STG_LDM + lane * 4;
                float e0 = d * (srow[0] + l0 * w64[0] + l1 * w65[0]);
                float e1 = d * (srow[1] + l0 * w64[1] + l1 * w65[1]);
                float e2 = d * (srow[2] + l0 * w64[2] + l1 * w65[2]);
                float e3 = d * (srow[3] + l0 * w64[3] + l1 * w65[3]);
                __half2 p0 = __floats2half2_rn(e0, e1);
                __half2 p1 = __floats2half2_rn(e2, e3);
                *(uint2*)&g_g1[t][(size_t)gr * H_ + lane * 4] =
                    make_uint2(*(unsigned*)&p0, *(unsigned*)&p1);
            }
        }
        __syncthreads();
    }
}

// ---------------- SpMM1 over half g1 -> g_colh only ----------------
__global__ void __launch_bounds__(256) k_spmm1(const float* __restrict__ b1,
                                               const float* __restrict__ W2) {
    int t = blockIdx.y;
    const __half* __restrict__ g = g_g1[t];

    __shared__ float w2c[H_];
    int tid = threadIdx.x;
    if (tid < H_) w2c[tid] = W2[(size_t)tid * H_ + (H_ - 1)];
    __syncthreads();

    int warp = tid >> 5, lane = tid & 31;
    int row = blockIdx.x * 8 + warp;
    if (row >= N_) return;

    int s0 = g_rowptr[t][row], s1 = g_rowptr[t][row + 1];
    const int* __restrict__ csr = g_csrsrc[t];
    int co = lane * 4;

    float ax = 0.f, ay = 0.f, az = 0.f, aw = 0.f;
    int j = s0;
    for (; j + 4 <= s1; j += 4) {
        int i0 = csr[j], i1 = csr[j + 1], i2 = csr[j + 2], i3 = csr[j + 3];
        uint2 r0 = *(const uint2*)&g[(size_t)i0 * H_ + co];
        uint2 r1 = *(const uint2*)&g[(size_t)i1 * H_ + co];
        uint2 r2 = *(const uint2*)&g[(size_t)i2 * H_ + co];
        uint2 r3 = *(const uint2*)&g[(size_t)i3 * H_ + co];
        float2 f;
        f = __half22float2(*(__half2*)&r0.x); ax += f.x; ay += f.y;
        f = __half22float2(*(__half2*)&r0.y); az += f.x; aw += f.y;
        f = __half22float2(*(__half2*)&r1.x); ax += f.x; ay += f.y;
        f = __half22float2(*(__half2*)&r1.y); az += f.x; aw += f.y;
        f = __half22float2(*(__half2*)&r2.x); ax += f.x; ay += f.y;
        f = __half22float2(*(__half2*)&r2.y); az += f.x; aw += f.y;
        f = __half22float2(*(__half2*)&r3.x); ax += f.x; ay += f.y;
        f = __half22float2(*(__half2*)&r3.y); az += f.x; aw += f.y;
    }
    for (; j < s1; j++) {
        uint2 r0 = *(const uint2*)&g[(size_t)csr[j] * H_ + co];
        float2 f;
        f = __half22float2(*(__half2*)&r0.x); ax += f.x; ay += f.y;
        f = __half22float2(*(__half2*)&r0.y); az += f.x; aw += f.y;
    }
    {
        uint2 r0 = *(const uint2*)&g[(size_t)row * H_ + co];
        float2 f;
        f = __half22float2(*(__half2*)&r0.x); ax += f.x; ay += f.y;
        f = __half22float2(*(__half2*)&r0.y); az += f.x; aw += f.y;
    }

    float d = g_dinv[t][row];
    float4 bb = *(const float4*)&b1[co];
    float h0 = fmaxf(fmaf(d, ax, bb.x), 0.f);
    float h1 = fmaxf(fmaf(d, ay, bb.y), 0.f);
    float h2 = fmaxf(fmaf(d, az, bb.z), 0.f);
    float h3 = fmaxf(fmaf(d, aw, bb.w), 0.f);

    float dot = h0 * w2c[co] + h1 * w2c[co + 1] + h2 * w2c[co + 2] + h3 * w2c[co + 3];
    dot = warp_sum(dot);
    if (lane == 0) g_colh[t][row] = __float2half(d * dot);
}

// ---------------- layer-2 scalar aggregation + fused argmax ----------------
__global__ void __launch_bounds__(256) k_col_argmax(const float* __restrict__ b2) {
    int t = blockIdx.y;
    int tid = threadIdx.x;
    int warp = tid >> 5, lane = tid & 31;
    int row = blockIdx.x * 8 + warp;
    unsigned long long p = 0ULL;
    float b = b2[H_ - 1];
    if (row < N_) {
        float d = g_dinv[t][row];
        if (d > 0.f) {
            int s0 = g_rowptr[t][row], s1 = g_rowptr[t][row + 1];
            const int* __restrict__ csr = g_csrsrc[t];
            const __half* __restrict__ col = g_colh[t];
            float s = 0.f;
            for (int j = s0 + lane; j < s1; j += 32) s += __half2float(col[csr[j]]);
            s = warp_sum(s);
            if (lane == 0) {
                float v = fmaxf(fmaf(d, s + __half2float(col[row]), b), 0.f);
                p = ((unsigned long long)__float_as_uint(v) << 32) |
                    (unsigned int)(0x7fffffff - row);
            }
        }
    }
    __shared__ unsigned long long sm[8];
    if (lane == 0) sm[warp] = p;
    __syncthreads();
    if (tid == 0) {
        unsigned long long m = sm[0];
#pragma unroll
        for (int i = 1; i < 8; i++) m = (sm[i] > m) ? sm[i] : m;
        if (m) atomicMax(&g_argmax[t], m);
    }
}

// ---------------- recompute h1 on top's nbhd; h2[top,:] -> g_seq ----------------
__global__ void __launch_bounds__(128) k_top(const float* __restrict__ b1,
                                             const float* __restrict__ W2,
                                             const float* __restrict__ b2) {
    int t = blockIdx.x;
    int top = 0x7fffffff - (int)(g_argmax[t] & 0x7fffffffULL);
    int c = threadIdx.x;
    __shared__ float svec[H_];
    const __half* __restrict__ g = g_g1[t];
    const int* __restrict__ csr = g_csrsrc[t];

    int s0 = g_rowptr[t][top], s1 = g_rowptr[t][top + 1];
    float sv = 0.f;
    float bc = b1[c];
    for (int idx = -1; idx < s1 - s0; idx++) {
        int u = (idx < 0) ? top : csr[s0 + idx];
        float du = g_dinv[t][u];
        if (du > 0.f) {
            int u0 = g_rowptr[t][u], u1 = g_rowptr[t][u + 1];
            float a0 = __half2float(g[(size_t)u * H_ + c]);
            float a1 = 0.f, a2 = 0.f, a3 = 0.f;
            int j = u0;
            for (; j + 4 <= u1; j += 4) {
                a0 += __half2float(g[(size_t)csr[j] * H_ + c]);
                a1 += __half2float(g[(size_t)csr[j + 1] * H_ + c]);
                a2 += __half2float(g[(size_t)csr[j + 2] * H_ + c]);
                a3 += __half2float(g[(size_t)csr[j + 3] * H_ + c]);
            }
            for (; j < u1; j++) a0 += __half2float(g[(size_t)csr[j] * H_ + c]);
            float agg = (a0 + a1) + (a2 + a3);
            float h = fmaxf(fmaf(du, agg, bc), 0.f);
            sv += du * h;
        }
    }
    svec[c] = sv;
    __syncthreads();

    float o = 0.f;
#pragma unroll 4
    for (int k = 0; k < H_; k++) o = fmaf(svec[k], W2[(size_t)k * H_ + c], o);
    float dtop = g_dinv[t][top];
    g_seq[t * H_ + c] = fmaxf(fmaf(dtop, o, b2[c]), 0.f);
}

// ---------------- GRU + MLP head ----------------
__global__ void __launch_bounds__(128) k_final(const float* __restrict__ Wih,
                                               const float* __restrict__ Whh,
                                               const float* __restrict__ bih,
                                               const float* __restrict__ bhh,
                                               const float* __restrict__ Wc1,
                                               const float* __restrict__ bc1,
                                               const float* __restrict__ Wc2,
                                               const float* __restrict__ bc2,
                                               float* __restrict__ out) {
    __shared__ float h[H_], xt[H_], sgi[3 * H_], sgh[3 * H_], hid[H_ / 2];
    int tid = threadIdx.x, lane = tid & 31, w = tid >> 5;
    h[tid] = 0.0f;
    __syncthreads();
    for (int t = 0; t < T_; t++) {
        xt[tid] = g_seq[t * H_ + tid];
        __syncthreads();
        for (int o = w; o < 3 * H_; o += 4) {
            float si = 0.f, sh = 0.f;
            for (int k = lane; k < H_; k += 32) {
                si += xt[k] * Wih[(size_t)o * H_ + k];
                sh += h[k] * Whh[(size_t)o * H_ + k];
            }
            si = warp_sum(si);
            sh = warp_sum(sh);
            if (lane == 0) {
                sgi[o] = si + bih[o];
                sgh[o] = sh + bhh[o];
            }
        }
        __syncthreads();
        float r = 1.0f / (1.0f + expf(-(sgi[tid] + sgh[tid])));
        float z = 1.0f / (1.0f + expf(-(sgi[tid + H_] + sgh[tid + H_])));
        float n = tanhf(sgi[tid + 2 * H_] + r * sgh[tid + 2 * H_]);
        float hn = (1.0f - z) * n + z * h[tid];
        __syncthreads();
        h[tid] = hn;
        __syncthreads();
    }
    if (tid < H_ / 2) {
        float s = bc1[tid];
        for (int k = 0; k < H_; k++) s += h[k] * Wc1[(size_t)k * (H_ / 2) + tid];
        hid[tid] = fmaxf(s, 0.0f);
    }
    __syncthreads();
    if (tid == 0) {
        float s = bc2[0];
        for (int j = 0; j < H_ / 2; j++) s += hid[j] * Wc2[j];
        out[0] = 1.0f / (1.0f + expf(-s));
    }
}

// ---------------- launch (fork-join) ----------------
extern "C" void kernel_launch(void* const* d_in, const int* in_sizes, int n_in,
                              void* d_out, int out_size) {
    const float* x   = (const float*)d_in[0];
    const int*   ei  = (const int*)d_in[1];
    const int*   tgt = (const int*)d_in[2];
    const float* W1  = (const float*)d_in[3];
    const float* b1  = (const float*)d_in[4];
    const float* W2  = (const float*)d_in[5];
    const float* b2  = (const float*)d_in[6];
    const float* Wih = (const float*)d_in[7];
    const float* Whh = (const float*)d_in[8];
    const float* bih = (const float*)d_in[9];
    const float* bhh = (const float*)d_in[10];
    const float* Wc1 = (const float*)d_in[11];
    const float* bc1 = (const float*)d_in[12];
    const float* Wc2 = (const float*)d_in[13];
    const float* bc2 = (const float*)d_in[14];
    float* out = (float*)d_out;

    const dim3 GI(80, T_);
    const dim3 GE((E_ + 255) / 256, T_);
    const dim3 GM((N_ + BM2 - 1) / BM2, T_);
    const dim3 GR((N_ + 7) / 8, T_);
    const dim3 GX((N_ * F_ / 4 + 255) / 256, T_);

    const int GEMM_SMEM = BM2 * A_LDM * 2 + F_ * H_ * 2;  // 34816 B
    static int smem_set = 0;
    if (!smem_set) {
        cudaFuncSetAttribute(k_gemm, cudaFuncAttributeMaxDynamicSharedMemorySize, GEMM_SMEM);
        smem_set = 1;
    }

    cudaStream_t s2;
    cudaStreamCreateWithFlags(&s2, cudaStreamNonBlocking);
    cudaEvent_t evF, evJ;
    cudaEventCreateWithFlags(&evF, cudaEventDisableTiming);
    cudaEventCreateWithFlags(&evJ, cudaEventDisableTiming);

    k_init<<<GI, 256>>>(tgt);

    // fork: side stream: half conversions + full-graph CSR
    cudaEventRecord(evF, cudaStreamPerThread);
    cudaStreamWaitEvent(s2, evF, 0);
    k_xhalf<<<GX, 256, 0, s2>>>(x);
    k_w1half<<<1, 256, 0, s2>>>(W1);
    k_count<<<GE, 256, 0, s2>>>(ei);
    k_scan<<<T_, 1024, 0, s2>>>();
    k_fill<<<GE, 256, 0, s2>>>(ei);
    cudaEventRecord(evJ, s2);

    // main stream: bitmask BFS
    k_prop1<<<GE, 256>>>(ei);
    k_prop2<<<GE, 256>>>(ei);

    // join
    cudaStreamWaitEvent(cudaStreamPerThread, evJ, 0);
    k_gemm<<<GM, 256, GEMM_SMEM>>>(W1);   // deg/dinv fused in prologue
    k_spmm1<<<GR, 256>>>(b1, W2);
    k_col_argmax<<<GR, 256>>>(b2);
    k_top<<<T_, 128>>>(b1, W2, b2);
    k_final<<<1, 128>>>(Wih, Whh, bih, bhh, Wc1, bc1, Wc2, bc2, out);

    cudaStreamCaptureStatus cs = cudaStreamCaptureStatusNone;
    cudaStreamIsCapturing(cudaStreamPerThread, &cs);
    cudaEventDestroy(evF);
    cudaEventDestroy(evJ);
    if (cs == cudaStreamCaptureStatusNone) cudaStreamDestroy(s2);
}

// round 11
// speedup vs baseline: 3.0649x; 3.0649x over previous
#include <cuda_runtime.h>
#include <cuda_fp16.h>
#include <mma.h>
#include <math.h>

using namespace nvcuda;

#define T_ 6
#define N_ 20000
#define E_ 400000
#define F_ 64
#define C_ 64
#define H_ 128
#define BIG_ 0x3fffffff

// ---------------- scratch (device globals; no allocation) ----------------
__device__ __align__(128) int    g_lvl[T_][N_];
__device__ __align__(128) int    g_count[T_][N_];
__device__ __align__(128) int    g_rowptr[T_][N_ + 1];
__device__ __align__(128) int    g_cursor[T_][N_];
__device__ __align__(128) int    g_csrsrc[T_][E_];
__device__ __align__(128) float  g_dinv[T_][N_];
__device__ __align__(128) __half g_xh[T_][N_ * F_];   // half copy of x
__device__ __align__(128) __half g_w1h[F_ * H_];      // half copy of W1[0:64]
__device__ __align__(128) __half g_g1[T_][N_ * H_];   // g1 = dinv*(xl@W1), fp16
__device__ __align__(128) float  g_col[T_][N_];       // dinv*(h1 . W2[:,127])
__device__ unsigned long long    g_argmax[T_];
__device__ __align__(128) float  g_seq[T_ * H_];
__device__ __align__(128) float  g_gi[T_][3 * H_];    // precomputed GRU input gates

// ---------------- init: lvl reset + seed + count zero + argmax zero ----------------
__global__ void k_init(const int* __restrict__ tgt) {
    int t = blockIdx.y;
    __shared__ int stgt[C_];
    if (threadIdx.x < C_) stgt[threadIdx.x] = tgt[t * C_ + threadIdx.x];
    __syncthreads();
    int i4 = (blockIdx.x * 256 + threadIdx.x) * 4;
    if (i4 < N_) {
        int4 v = make_int4(BIG_, BIG_, BIG_, BIG_);
#pragma unroll
        for (int j = 0; j < C_; j++) {
            int tg = stgt[j];
            if (tg == i4) v.x = 0;
            if (tg == i4 + 1) v.y = 0;
            if (tg == i4 + 2) v.z = 0;
            if (tg == i4 + 3) v.w = 0;
        }
        *(int4*)&g_lvl[t][i4] = v;
        *(int4*)&g_count[t][i4] = make_int4(0, 0, 0, 0);
    }
    if (blockIdx.x == 0 && threadIdx.x == 0) g_argmax[t] = 0ULL;
}

// ---------------- half conversions (fork branch) ----------------
__global__ void k_xhalf(const float* __restrict__ x) {
    int t = blockIdx.y;
    int i4 = (blockIdx.x * 256 + threadIdx.x) * 4;
    if (i4 >= N_ * F_) return;
    float4 v = *(const float4*)&x[(size_t)t * N_ * F_ + i4];
    __half2 p0 = __floats2half2_rn(v.x, v.y);
    __half2 p1 = __floats2half2_rn(v.z, v.w);
    *(uint2*)&g_xh[t][i4] = make_uint2(*(unsigned*)&p0, *(unsigned*)&p1);
}

__global__ void k_w1half(const float* __restrict__ W1) {
    for (int i = threadIdx.x * 2; i < F_ * H_; i += 512) {
        __half2 p = __floats2half2_rn(W1[i], W1[i + 1]);
        *(unsigned*)&g_w1h[i] = *(unsigned*)&p;
    }
}

// ---------------- BFS (level-stamped; writes during iter k are exactly k) ----------
__global__ void k_prop(const int* __restrict__ ei, int k) {
    int t = blockIdx.y;
    int i = blockIdx.x * blockDim.x + threadIdx.x;
    if (i >= E_) return;
    const int* src = ei + (size_t)t * 2 * E_;
    const int* dst = src + E_;
    int s = src[i], d = dst[i];
    int ls = g_lvl[t][s], ld = g_lvl[t][d];
    if (ls < k && ld > k) atomicMin(&g_lvl[t][d], k);
    if (ld < k && ls > k) atomicMin(&g_lvl[t][s], k);
}

// ---------------- CSR branch (FULL graph) ----------------
__global__ void k_count(const int* __restrict__ ei) {
    int t = blockIdx.y;
    int i = blockIdx.x * blockDim.x + threadIdx.x;
    if (i >= E_) return;
    const int* dst = ei + (size_t)t * 2 * E_ + E_;
    atomicAdd(&g_count[t][dst[i]], 1);
}

__global__ void k_scan() {
    int t = blockIdx.x;
    const int CH = 20;
    __shared__ int s[1024];
    int tid = threadIdx.x;
    int base = tid * CH;
    int loc[CH];
    int sum = 0;
#pragma unroll
    for (int i = 0; i < CH; i++) {
        int idx = base + i;
        int c = (idx < N_) ? g_count[t][idx] : 0;
        loc[i] = sum;
        sum += c;
    }
    s[tid] = sum;
    __syncthreads();
    for (int off = 1; off < 1024; off <<= 1) {
        int v = (tid >= off) ? s[tid - off] : 0;
        __syncthreads();
        s[tid] += v;
        __syncthreads();
    }
    int excl = s[tid] - sum;
#pragma unroll
    for (int i = 0; i < CH; i++) {
        int idx = base + i;
        if (idx < N_) {
            int o = excl + loc[i];
            g_rowptr[t][idx] = o;
            g_cursor[t][idx] = o;
        }
    }
    if (tid == 1023) g_rowptr[t][N_] = s[1023];
}

__global__ void k_fill(const int* __restrict__ ei) {
    int t = blockIdx.y;
    int i = blockIdx.x * blockDim.x + threadIdx.x;
    if (i >= E_) return;
    const int* src = ei + (size_t)t * 2 * E_;
    const int* dst = src + E_;
    int s = src[i], d = dst[i];
    int p = atomicAdd(&g_cursor[t][d], 1);
    g_csrsrc[t][p] = s;
}

// ---------------- join: subgraph degree + dinv ----------------
__global__ void __launch_bounds__(256) k_deg() {
    int t = blockIdx.y;
    int tid = threadIdx.x;
    int warp = tid >> 5, lane = tid & 31;
    int row = blockIdx.x * 8 + warp;
    if (row >= N_) return;
    const int* __restrict__ lvl = g_lvl[t];
    bool in = lvl[row] < BIG_;
    int cnt = 0;
    if (in) {
        int s0 = g_rowptr[t][row], s1 = g_rowptr[t][row + 1];
        const int* __restrict__ csr = g_csrsrc[t];
        for (int j = s0 + lane; j < s1; j += 32) cnt += (lvl[csr[j]] < BIG_) ? 1 : 0;
    }
    cnt += __shfl_down_sync(0xffffffffu, cnt, 16);
    cnt += __shfl_down_sync(0xffffffffu, cnt, 8);
    cnt += __shfl_down_sync(0xffffffffu, cnt, 4);
    cnt += __shfl_down_sync(0xffffffffu, cnt, 2);
    cnt += __shfl_down_sync(0xffffffffu, cnt, 1);
    if (lane == 0) g_dinv[t][row] = in ? rsqrtf((float)cnt + 1.0f) : 0.0f;
}

// ---------------- tensor-core GEMM: g1(half) = dinv * ([x,labels] @ W1) ------------
#define BM2 128
#define A_LDM 72
#define STG_LDM 136
__global__ void __launch_bounds__(256) k_gemm(const float* __restrict__ W1) {
    extern __shared__ char smraw[];
    __half* Axs = (__half*)smraw;                       // [128][72]
    __half* W1s = (__half*)(smraw + BM2 * A_LDM * 2);   // [64][128]
    float* stg = (float*)smraw;                         // [4][16][136] (phase 2)

    int t = blockIdx.y;
    int tid = threadIdx.x;
    int warp = tid >> 5, lane = tid & 31;
    int m0 = blockIdx.x * BM2;
    const __half* __restrict__ xh = g_xh[t];

#pragma unroll
    for (int i = 0; i < 4; i++) {
        int e = tid + i * 256;
        int r = e >> 3, q = e & 7;
        int gr = m0 + r;
        uint4 v = make_uint4(0, 0, 0, 0);
        if (gr < N_) v = *(const uint4*)&xh[(size_t)gr * F_ + q * 8];
        *(uint4*)&Axs[r * A_LDM + q * 8] = v;
    }
#pragma unroll
    for (int i = 0; i < 4; i++) {
        int e = tid + i * 256;
        int r = e >> 4, q = e & 15;
        *(uint4*)&W1s[r * H_ + q * 8] = *(const uint4*)&g_w1h[r * H_ + q * 8];
    }
    __syncthreads();

    wmma::fragment<wmma::accumulator, 16, 16, 16, float> acc[8];
#pragma unroll
    for (int nt = 0; nt < 8; nt++) wmma::fill_fragment(acc[nt], 0.0f);

#pragma unroll
    for (int ks = 0; ks < 4; ks++) {
        wmma::fragment<wmma::matrix_a, 16, 16, 16, __half, wmma::row_major> af;
        wmma::load_matrix_sync(af, Axs + warp * 16 * A_LDM + ks * 16, A_LDM);
#pragma unroll
        for (int nt = 0; nt < 8; nt++) {
            wmma::fragment<wmma::matrix_b, 16, 16, 16, __half, wmma::row_major> bf;
            wmma::load_matrix_sync(bf, W1s + ks * 16 * H_ + nt * 16, H_);
            wmma::mma_sync(acc[nt], af, bf, acc[nt]);
        }
    }
    __syncthreads();

    float w64[4], w65[4];
#pragma unroll
    for (int j = 0; j < 4; j++) {
        w64[j] = W1[(size_t)64 * H_ + lane * 4 + j];
        w65[j] = W1[(size_t)65 * H_ + lane * 4 + j];
    }

#pragma unroll
    for (int grp = 0; grp < 2; grp++) {
        bool mine = (warp >> 2) == grp;
        int wslot = warp & 3;
        if (mine) {
#pragma unroll
            for (int nt = 0; nt < 8; nt++)
                wmma::store_matrix_sync(stg + wslot * 16 * STG_LDM + nt * 16, acc[nt],
                                        STG_LDM, wmma::mem_row_major);
        }
        __syncthreads();
        if (mine) {
            for (int r = 0; r < 16; r++) {
                int gr = m0 + warp * 16 + r;
                if (gr >= N_) break;
                int lv = g_lvl[t][gr];
                float l0 = (lv == 0) ? 1.0f : 0.0f;
                float l1 = (lv > 0 && lv < BIG_) ? 1.0f : 0.0f;
                float d = g_dinv[t][gr];
                const float* srow = stg + wslot * 16 * STG_LDM + r * STG_LDM + lane * 4;
                float e0 = d * (srow[0] + l0 * w64[0] + l1 * w65[0]);
                float e1 = d * (srow[1] + l0 * w64[1] + l1 * w65[1]);
                float e2 = d * (srow[2] + l0 * w64[2] + l1 * w65[2]);
                float e3 = d * (srow[3] + l0 * w64[3] + l1 * w65[3]);
                __half2 p0 = __floats2half2_rn(e0, e1);
                __half2 p1 = __floats2half2_rn(e2, e3);
                *(uint2*)&g_g1[t][(size_t)gr * H_ + lane * 4] =
                    make_uint2(*(unsigned*)&p0, *(unsigned*)&p1);
            }
        }
        __syncthreads();
    }
}

__device__ __forceinline__ float warp_sum(float v) {
    v += __shfl_down_sync(0xffffffffu, v, 16);
    v += __shfl_down_sync(0xffffffffu, v, 8);
    v += __shfl_down_sync(0xffffffffu, v, 4);
    v += __shfl_down_sync(0xffffffffu, v, 2);
    v += __shfl_down_sync(0xffffffffu, v, 1);
    return v;
}

// ---------------- SpMM1 over half g1 -> g_col only ----------------
__global__ void __launch_bounds__(256) k_spmm1(const float* __restrict__ b1,
                                               const float* __restrict__ W2) {
    int t = blockIdx.y;
    const __half* __restrict__ g = g_g1[t];

    __shared__ float w2c[H_];
    int tid = threadIdx.x;
    if (tid < H_) w2c[tid] = W2[(size_t)tid * H_ + (H_ - 1)];
    __syncthreads();

    int warp = tid >> 5, lane = tid & 31;
    int row = blockIdx.x * 8 + warp;
    if (row >= N_) return;

    int s0 = g_rowptr[t][row], s1 = g_rowptr[t][row + 1];
    const int* __restrict__ csr = g_csrsrc[t];
    int co = lane * 4;

    float ax = 0.f, ay = 0.f, az = 0.f, aw = 0.f;
    int j = s0;
    for (; j + 4 <= s1; j += 4) {
        int i0 = csr[j], i1 = csr[j + 1], i2 = csr[j + 2], i3 = csr[j + 3];
        uint2 r0 = *(const uint2*)&g[(size_t)i0 * H_ + co];
        uint2 r1 = *(const uint2*)&g[(size_t)i1 * H_ + co];
        uint2 r2 = *(const uint2*)&g[(size_t)i2 * H_ + co];
        uint2 r3 = *(const uint2*)&g[(size_t)i3 * H_ + co];
        float2 f;
        f = __half22float2(*(__half2*)&r0.x); ax += f.x; ay += f.y;
        f = __half22float2(*(__half2*)&r0.y); az += f.x; aw += f.y;
        f = __half22float2(*(__half2*)&r1.x); ax += f.x; ay += f.y;
        f = __half22float2(*(__half2*)&r1.y); az += f.x; aw += f.y;
        f = __half22float2(*(__half2*)&r2.x); ax += f.x; ay += f.y;
        f = __half22float2(*(__half2*)&r2.y); az += f.x; aw += f.y;
        f = __half22float2(*(__half2*)&r3.x); ax += f.x; ay += f.y;
        f = __half22float2(*(__half2*)&r3.y); az += f.x; aw += f.y;
    }
    for (; j < s1; j++) {
        uint2 r0 = *(const uint2*)&g[(size_t)csr[j] * H_ + co];
        float2 f;
        f = __half22float2(*(__half2*)&r0.x); ax += f.x; ay += f.y;
        f = __half22float2(*(__half2*)&r0.y); az += f.x; aw += f.y;
    }
    {
        uint2 r0 = *(const uint2*)&g[(size_t)row * H_ + co];
        float2 f;
        f = __half22float2(*(__half2*)&r0.x); ax += f.x; ay += f.y;
        f = __half22float2(*(__half2*)&r0.y); az += f.x; aw += f.y;
    }

    float d = g_dinv[t][row];
    float4 bb = *(const float4*)&b1[co];
    float h0 = fmaxf(fmaf(d, ax, bb.x), 0.f);
    float h1 = fmaxf(fmaf(d, ay, bb.y), 0.f);
    float h2 = fmaxf(fmaf(d, az, bb.z), 0.f);
    float h3 = fmaxf(fmaf(d, aw, bb.w), 0.f);

    float dot = h0 * w2c[co] + h1 * w2c[co + 1] + h2 * w2c[co + 2] + h3 * w2c[co + 3];
    dot = warp_sum(dot);
    if (lane == 0) g_col[t][row] = d * dot;
}

// ---------------- layer-2 scalar aggregation + fused argmax ----------------
__global__ void __launch_bounds__(256) k_col_argmax(const float* __restrict__ b2) {
    int t = blockIdx.y;
    int tid = threadIdx.x;
    int warp = tid >> 5, lane = tid & 31;
    int row = blockIdx.x * 8 + warp;
    unsigned long long p = 0ULL;
    float b = b2[H_ - 1];
    if (row < N_) {
        int s0 = g_rowptr[t][row], s1 = g_rowptr[t][row + 1];
        const int* __restrict__ csr = g_csrsrc[t];
        const float* __restrict__ col = g_col[t];
        float s = 0.f;
        for (int j = s0 + lane; j < s1; j += 32) s += col[csr[j]];
        s = warp_sum(s);
        if (lane == 0) {
            float d = g_dinv[t][row];
            if (d > 0.f) {
                float v = fmaxf(fmaf(d, s + col[row], b), 0.f);
                p = ((unsigned long long)__float_as_uint(v) << 32) |
                    (unsigned int)(0x7fffffff - row);
            }
        }
    }
    __shared__ unsigned long long sm[8];
    if (lane == 0) sm[warp] = p;
    __syncthreads();
    if (tid == 0) {
        unsigned long long m = sm[0];
#pragma unroll
        for (int i = 1; i < 8; i++) m = (sm[i] > m) ? sm[i] : m;
        if (m) atomicMax(&g_argmax[t], m);
    }
}

// ---------------- k_top v2: warp-per-neighbor recompute of h1; h2[top,:] -> g_seq ---
__global__ void __launch_bounds__(256) k_top(const float* __restrict__ b1,
                                             const float* __restrict__ W2,
                                             const float* __restrict__ b2) {
    int t = blockIdx.x;
    int top = 0x7fffffff - (int)(g_argmax[t] & 0x7fffffffULL);
    int tid = threadIdx.x;
    int warp = tid >> 5, lane = tid & 31;
    __shared__ float svec[H_];
    const __half* __restrict__ g = g_g1[t];
    const int* __restrict__ csr = g_csrsrc[t];

    if (tid < H_) svec[tid] = 0.f;
    __syncthreads();

    int s0 = g_rowptr[t][top], s1 = g_rowptr[t][top + 1];
    int nU = 1 + (s1 - s0);   // u_idx 0 = top itself; else csr[s0 + u_idx - 1]
    int co = lane * 4;

    for (int ui = warp; ui < nU; ui += 8) {
        int u = (ui == 0) ? top : csr[s0 + ui - 1];
        float du = g_dinv[t][u];
        if (du <= 0.f) continue;
        int u0 = g_rowptr[t][u], u1 = g_rowptr[t][u + 1];
        float ax = 0.f, ay = 0.f, az = 0.f, aw = 0.f;
        int j = u0;
        for (; j + 4 <= u1; j += 4) {
            uint2 r0 = *(const uint2*)&g[(size_t)csr[j] * H_ + co];
            uint2 r1 = *(const uint2*)&g[(size_t)csr[j + 1] * H_ + co];
            uint2 r2 = *(const uint2*)&g[(size_t)csr[j + 2] * H_ + co];
            uint2 r3 = *(const uint2*)&g[(size_t)csr[j + 3] * H_ + co];
            float2 f;
            f = __half22float2(*(__half2*)&r0.x); ax += f.x; ay += f.y;
            f = __half22float2(*(__half2*)&r0.y); az += f.x; aw += f.y;
            f = __half22float2(*(__half2*)&r1.x); ax += f.x; ay += f.y;
            f = __half22float2(*(__half2*)&r1.y); az += f.x; aw += f.y;
            f = __half22float2(*(__half2*)&r2.x); ax += f.x; ay += f.y;
            f = __half22float2(*(__half2*)&r2.y); az += f.x; aw += f.y;
            f = __half22float2(*(__half2*)&r3.x); ax += f.x; ay += f.y;
            f = __half22float2(*(__half2*)&r3.y); az += f.x; aw += f.y;
        }
        for (; j < u1; j++) {
            uint2 r0 = *(const uint2*)&g[(size_t)csr[j] * H_ + co];
            float2 f;
            f = __half22float2(*(__half2*)&r0.x); ax += f.x; ay += f.y;
            f = __half22float2(*(__half2*)&r0.y); az += f.x; aw += f.y;
        }
        {   // self term of u
            uint2 r0 = *(const uint2*)&g[(size_t)u * H_ + co];
            float2 f;
            f = __half22float2(*(__half2*)&r0.x); ax += f.x; ay += f.y;
            f = __half22float2(*(__half2*)&r0.y); az += f.x; aw += f.y;
        }
        float h0 = fmaxf(fmaf(du, ax, b1[co + 0]), 0.f);
        float h1 = fmaxf(fmaf(du, ay, b1[co + 1]), 0.f);
        float h2 = fmaxf(fmaf(du, az, b1[co + 2]), 0.f);
        float h3 = fmaxf(fmaf(du, aw, b1[co + 3]), 0.f);
        atomicAdd(&svec[co + 0], du * h0);
        atomicAdd(&svec[co + 1], du * h1);
        atomicAdd(&svec[co + 2], du * h2);
        atomicAdd(&svec[co + 3], du * h3);
    }
    __syncthreads();

    if (tid < H_) {
        float o = 0.f;
        int c = tid;
#pragma unroll 4
        for (int k = 0; k < H_; k++) o = fmaf(svec[k], W2[(size_t)k * H_ + c], o);
        float dtop = g_dinv[t][top];
        g_seq[t * H_ + c] = fmaxf(fmaf(dtop, o, b2[c]), 0.f);
    }
}

// ---------------- GRU input gates (parallel over t,o): gi = xt@Wih.T + bih ----------
__global__ void __launch_bounds__(256) k_gi(const float* __restrict__ Wih,
                                            const float* __restrict__ bih) {
    int w = (blockIdx.x * 256 + threadIdx.x) >> 5;   // global warp = output index
    int lane = threadIdx.x & 31;
    if (w >= T_ * 3 * H_) return;
    int t = w / (3 * H_);
    int o = w - t * (3 * H_);
    float4 xv = *(const float4*)&g_seq[t * H_ + lane * 4];
    float4 wv = *(const float4*)&Wih[(size_t)o * H_ + lane * 4];
    float s = xv.x * wv.x + xv.y * wv.y + xv.z * wv.z + xv.w * wv.w;
    s = warp_sum(s);
    if (lane == 0) g_gi[t][o] = s + bih[o];
}

// ---------------- GRU recurrence + MLP head; Whh^T cached in smem (fp32) ----------
__global__ void __launch_bounds__(384) k_gru(const float* __restrict__ Whh,
                                             const float* __restrict__ bhh,
                                             const float* __restrict__ Wc1,
                                             const float* __restrict__ bc1,
                                             const float* __restrict__ Wc2,
                                             const float* __restrict__ bc2,
                                             float* __restrict__ out) {
    extern __shared__ float sW[];          // [128][385] : sW[k*385+o] = Whh[o][k]
    __shared__ float sh[H_], sgh[3 * H_], shid[H_ / 2];
    int tid = threadIdx.x;

    // fill transposed Whh (coalesced read; padded stride kills write conflicts)
    for (int e = tid * 4; e < 3 * H_ * H_; e += 384 * 4) {
        float4 v = *(const float4*)&Whh[e];
        int o = e >> 7;           // e / 128
        int k = e & 127;
        sW[(k + 0) * 385 + o] = v.x;
        sW[(k + 1) * 385 + o] = v.y;
        sW[(k + 2) * 385 + o] = v.z;
        sW[(k + 3) * 385 + o] = v.w;
    }
    if (tid < H_) sh[tid] = 0.f;
    float mybhh = bhh[tid];
    __syncthreads();

    for (int t = 0; t < T_; t++) {
        float acc = mybhh;
#pragma unroll 8
        for (int k = 0; k < H_; k++) acc = fmaf(sh[k], sW[k * 385 + tid], acc);
        sgh[tid] = acc;
        __syncthreads();
        float hn = 0.f;
        if (tid < H_) {
            float r = 1.0f / (1.0f + expf(-(g_gi[t][tid] + sgh[tid])));
            float z = 1.0f / (1.0f + expf(-(g_gi[t][tid + H_] + sgh[tid + H_])));
            float n = tanhf(g_gi[t][tid + 2 * H_] + r * sgh[tid + 2 * H_]);
            hn = (1.0f - z) * n + z * sh[tid];
        }
        __syncthreads();
        if (tid < H_) sh[tid] = hn;
        __syncthreads();
    }

    if (tid < H_ / 2) {
        float s = bc1[tid];
        for (int k = 0; k < H_; k++) s += sh[k] * Wc1[(size_t)k * (H_ / 2) + tid];
        shid[tid] = fmaxf(s, 0.0f);
    }
    __syncthreads();
    if (tid == 0) {
        float s = bc2[0];
        for (int j = 0; j < H_ / 2; j++) s += shid[j] * Wc2[j];
        out[0] = 1.0f / (1.0f + expf(-s));
    }
}

// ---------------- launch (fork-join) ----------------
extern "C" void kernel_launch(void* const* d_in, const int* in_sizes, int n_in,
                              void* d_out, int out_size) {
    const float* x   = (const float*)d_in[0];
    const int*   ei  = (const int*)d_in[1];
    const int*   tgt = (const int*)d_in[2];
    const float* W1  = (const float*)d_in[3];
    const float* b1  = (const float*)d_in[4];
    const float* W2  = (const float*)d_in[5];
    const float* b2  = (const float*)d_in[6];
    const float* Wih = (const float*)d_in[7];
    const float* Whh = (const float*)d_in[8];
    const float* bih = (const float*)d_in[9];
    const float* bhh = (const float*)d_in[10];
    const float* Wc1 = (const float*)d_in[11];
    const float* bc1 = (const float*)d_in[12];
    const float* Wc2 = (const float*)d_in[13];
    const float* bc2 = (const float*)d_in[14];
    float* out = (float*)d_out;

    const dim3 GRST((N_ / 4 + 255) / 256, T_);
    const dim3 GE((E_ + 255) / 256, T_);
    const dim3 GM((N_ + BM2 - 1) / BM2, T_);
    const dim3 GR((N_ + 7) / 8, T_);
    const dim3 GX((N_ * F_ / 4 + 255) / 256, T_);
    const int GI_BLOCKS = (T_ * 3 * H_ * 32 + 255) / 256;

    const int GEMM_SMEM = BM2 * A_LDM * 2 + F_ * H_ * 2;  // 34816 B
    const int GRU_SMEM = H_ * 385 * (int)sizeof(float);    // 197120 B
    static int smem_set = 0;
    if (!smem_set) {
        cudaFuncSetAttribute(k_gemm, cudaFuncAttributeMaxDynamicSharedMemorySize, GEMM_SMEM);
        cudaFuncSetAttribute(k_gru, cudaFuncAttributeMaxDynamicSharedMemorySize, GRU_SMEM);
        smem_set = 1;
    }

    cudaStream_t s2;
    cudaStreamCreateWithFlags(&s2, cudaStreamNonBlocking);
    cudaEvent_t evF, evJ;
    cudaEventCreateWithFlags(&evF, cudaEventDisableTiming);
    cudaEventCreateWithFlags(&evJ, cudaEventDisableTiming);

    k_init<<<GRST, 256>>>(tgt);

    // fork: side stream: half conversions + full-graph CSR
    cudaEventRecord(evF, cudaStreamPerThread);
    cudaStreamWaitEvent(s2, evF, 0);
    k_xhalf<<<GX, 256, 0, s2>>>(x);
    k_w1half<<<1, 256, 0, s2>>>(W1);
    k_count<<<GE, 256, 0, s2>>>(ei);
    k_scan<<<T_, 1024, 0, s2>>>();
    k_fill<<<GE, 256, 0, s2>>>(ei);
    cudaEventRecord(evJ, s2);

    // main stream: BFS
    k_prop<<<GE, 256>>>(ei, 1);
    k_prop<<<GE, 256>>>(ei, 2);

    // join
    cudaStreamWaitEvent(cudaStreamPerThread, evJ, 0);
    k_deg<<<GR, 256>>>();
    k_gemm<<<GM, 256, GEMM_SMEM>>>(W1);
    k_spmm1<<<GR, 256>>>(b1, W2);
    k_col_argmax<<<GR, 256>>>(b2);
    k_top<<<T_, 256>>>(b1, W2, b2);
    k_gi<<<GI_BLOCKS, 256>>>(Wih, bih);
    k_gru<<<1, 384, GRU_SMEM>>>(Whh, bhh, Wc1, bc1, Wc2, bc2, out);

    cudaStreamCaptureStatus cs = cudaStreamCaptureStatusNone;
    cudaStreamIsCapturing(cudaStreamPerThread, &cs);
    cudaEventDestroy(evF);
    cudaEventDestroy(evJ);
    if (cs == cudaStreamCaptureStatusNone) cudaStreamDestroy(s2);
}

// round 13
// speedup vs baseline: 3.3209x; 1.0835x over previous
#include <cuda_runtime.h>
#include <cuda_fp16.h>
#include <mma.h>
#include <math.h>

using namespace nvcuda;

#define T_ 6
#define N_ 20000
#define E_ 400000
#define F_ 64
#define C_ 64
#define H_ 128
#define BIG_ 0x3fffffff
#define CAP_ 128   // bucket capacity per node (max full-graph in-degree ~55; pow2)

// ---------------- scratch (device globals; no allocation) ----------------
__device__ __align__(128) int    g_lvl[T_][N_];
__device__ __align__(128) int    g_cnt[T_][N_];        // bucket fill counters
__device__ __align__(128) int    g_sdeg[T_][N_];       // subgraph in-degree
__device__ __align__(128) int    g_bucket[T_][N_ * CAP_];
__device__ __align__(128) float  g_dinv[T_][N_];
__device__ __align__(128) __half g_xh[T_][N_ * F_];
__device__ __align__(128) __half g_w1h[F_ * H_];
__device__ __align__(128) __half g_g1[T_][N_ * H_];
__device__ __align__(128) float  g_col[T_][N_];
__device__ unsigned long long    g_argmax[T_];
__device__ __align__(128) float  g_seq[T_ * H_];
__device__ __align__(128) float  g_gi[T_][3 * H_];

// ---------------- init: lvl reset + seed + counters + argmax ----------------
__global__ void k_init(const int* __restrict__ tgt) {
    int t = blockIdx.y;
    __shared__ int stgt[C_];
    if (threadIdx.x < C_) stgt[threadIdx.x] = tgt[t * C_ + threadIdx.x];
    __syncthreads();
    int i4 = (blockIdx.x * 256 + threadIdx.x) * 4;
    if (i4 < N_) {
        int4 v = make_int4(BIG_, BIG_, BIG_, BIG_);
#pragma unroll
        for (int j = 0; j < C_; j++) {
            int tg = stgt[j];
            if (tg == i4) v.x = 0;
            if (tg == i4 + 1) v.y = 0;
            if (tg == i4 + 2) v.z = 0;
            if (tg == i4 + 3) v.w = 0;
        }
        *(int4*)&g_lvl[t][i4] = v;
        *(int4*)&g_cnt[t][i4] = make_int4(0, 0, 0, 0);
        *(int4*)&g_sdeg[t][i4] = make_int4(0, 0, 0, 0);
    }
    if (blockIdx.x == 0 && threadIdx.x == 0) g_argmax[t] = 0ULL;
}

// ---------------- half conversions (side stream, early) ----------------
__global__ void k_xhalf(const float* __restrict__ x) {
    int t = blockIdx.y;
    int i4 = (blockIdx.x * 256 + threadIdx.x) * 4;
    if (i4 >= N_ * F_) return;
    float4 v = *(const float4*)&x[(size_t)t * N_ * F_ + i4];
    __half2 p0 = __floats2half2_rn(v.x, v.y);
    __half2 p1 = __floats2half2_rn(v.z, v.w);
    *(uint2*)&g_xh[t][i4] = make_uint2(*(unsigned*)&p0, *(unsigned*)&p1);
}

__global__ void k_w1half(const float* __restrict__ W1) {
    for (int i = threadIdx.x * 2; i < F_ * H_; i += 512) {
        __half2 p = __floats2half2_rn(W1[i], W1[i + 1]);
        *(unsigned*)&g_w1h[i] = *(unsigned*)&p;
    }
}

// ---------------- BFS (level-stamped; writes during iter k are exactly k) ----------
__global__ void k_prop(const int* __restrict__ ei, int k) {
    int t = blockIdx.y;
    int i = blockIdx.x * blockDim.x + threadIdx.x;
    if (i >= E_) return;
    const int* src = ei + (size_t)t * 2 * E_;
    const int* dst = src + E_;
    int s = src[i], d = dst[i];
    int ls = g_lvl[t][s], ld = g_lvl[t][d];
    if (ls < k && ld > k) atomicMin(&g_lvl[t][d], k);
    if (ld < k && ls > k) atomicMin(&g_lvl[t][s], k);
}

// ---------------- edge-centric subgraph degree (main stream; no CSR needed) -------
__global__ void k_edeg(const int* __restrict__ ei) {
    int t = blockIdx.y;
    int i = blockIdx.x * blockDim.x + threadIdx.x;
    if (i >= E_) return;
    const int* src = ei + (size_t)t * 2 * E_;
    const int* dst = src + E_;
    int s = src[i], d = dst[i];
    if (g_lvl[t][s] < BIG_ && g_lvl[t][d] < BIG_) atomicAdd(&g_sdeg[t][d], 1);
}

__global__ void k_dinv() {
    int t = blockIdx.y;
    int i = blockIdx.x * 256 + threadIdx.x;
    if (i >= N_) return;
    bool in = g_lvl[t][i] < BIG_;
    g_dinv[t][i] = in ? rsqrtf((float)g_sdeg[t][i] + 1.0f) : 0.0f;
}

// ---------------- bucket-CSR fill (side stream; full graph, no scan) ----------------
__global__ void k_fill(const int* __restrict__ ei) {
    int t = blockIdx.y;
    int i = blockIdx.x * blockDim.x + threadIdx.x;
    if (i >= E_) return;
    const int* src = ei + (size_t)t * 2 * E_;
    const int* dst = src + E_;
    int s = src[i], d = dst[i];
    int p = atomicAdd(&g_cnt[t][d], 1);
    if (p < CAP_) g_bucket[t][d * CAP_ + p] = s;
}

// ---------------- tensor-core GEMM: g1(half) = dinv * ([x,labels] @ W1) ------------
#define BM2 128
#define A_LDM 72
#define STG_LDM 136
__global__ void __launch_bounds__(256) k_gemm(const float* __restrict__ W1) {
    extern __shared__ char smraw[];
    __half* Axs = (__half*)smraw;
    __half* W1s = (__half*)(smraw + BM2 * A_LDM * 2);
    float* stg = (float*)smraw;

    int t = blockIdx.y;
    int tid = threadIdx.x;
    int warp = tid >> 5, lane = tid & 31;
    int m0 = blockIdx.x * BM2;
    const __half* __restrict__ xh = g_xh[t];

#pragma unroll
    for (int i = 0; i < 4; i++) {
        int e = tid + i * 256;
        int r = e >> 3, q = e & 7;
        int gr = m0 + r;
        uint4 v = make_uint4(0, 0, 0, 0);
        if (gr < N_) v = *(const uint4*)&xh[(size_t)gr * F_ + q * 8];
        *(uint4*)&Axs[r * A_LDM + q * 8] = v;
    }
#pragma unroll
    for (int i = 0; i < 4; i++) {
        int e = tid + i * 256;
        int r = e >> 4, q = e & 15;
        *(uint4*)&W1s[r * H_ + q * 8] = *(const uint4*)&g_w1h[r * H_ + q * 8];
    }
    __syncthreads();

    wmma::fragment<wmma::accumulator, 16, 16, 16, float> acc[8];
#pragma unroll
    for (int nt = 0; nt < 8; nt++) wmma::fill_fragment(acc[nt], 0.0f);

#pragma unroll
    for (int ks = 0; ks < 4; ks++) {
        wmma::fragment<wmma::matrix_a, 16, 16, 16, __half, wmma::row_major> af;
        wmma::load_matrix_sync(af, Axs + warp * 16 * A_LDM + ks * 16, A_LDM);
#pragma unroll
        for (int nt = 0; nt < 8; nt++) {
            wmma::fragment<wmma::matrix_b, 16, 16, 16, __half, wmma::row_major> bf;
            wmma::load_matrix_sync(bf, W1s + ks * 16 * H_ + nt * 16, H_);
            wmma::mma_sync(acc[nt], af, bf, acc[nt]);
        }
    }
    __syncthreads();

    float w64[4], w65[4];
#pragma unroll
    for (int j = 0; j < 4; j++) {
        w64[j] = W1[(size_t)64 * H_ + lane * 4 + j];
        w65[j] = W1[(size_t)65 * H_ + lane * 4 + j];
    }

#pragma unroll
    for (int grp = 0; grp < 2; grp++) {
        bool mine = (warp >> 2) == grp;
        int wslot = warp & 3;
        if (mine) {
#pragma unroll
            for (int nt = 0; nt < 8; nt++)
                wmma::store_matrix_sync(stg + wslot * 16 * STG_LDM + nt * 16, acc[nt],
                                        STG_LDM, wmma::mem_row_major);
        }
        __syncthreads();
        if (mine) {
            for (int r = 0; r < 16; r++) {
                int gr = m0 + warp * 16 + r;
                if (gr >= N_) break;
                int lv = g_lvl[t][gr];
                float l0 = (lv == 0) ? 1.0f : 0.0f;
                float l1 = (lv > 0 && lv < BIG_) ? 1.0f : 0.0f;
                float d = g_dinv[t][gr];
                const float* srow = stg + wslot * 16 * STG_LDM + r * STG_LDM + lane * 4;
                float e0 = d * (srow[0] + l0 * w64[0] + l1 * w65[0]);
                float e1 = d * (srow[1] + l0 * w64[1] + l1 * w65[1]);
                float e2 = d * (srow[2] + l0 * w64[2] + l1 * w65[2]);
                float e3 = d * (srow[3] + l0 * w64[3] + l1 * w65[3]);
                __half2 p0 = __floats2half2_rn(e0, e1);
                __half2 p1 = __floats2half2_rn(e2, e3);
                *(uint2*)&g_g1[t][(size_t)gr * H_ + lane * 4] =
                    make_uint2(*(unsigned*)&p0, *(unsigned*)&p1);
            }
        }
        __syncthreads();
    }
}

__device__ __forceinline__ float warp_sum(float v) {
    v += __shfl_down_sync(0xffffffffu, v, 16);
    v += __shfl_down_sync(0xffffffffu, v, 8);
    v += __shfl_down_sync(0xffffffffu, v, 4);
    v += __shfl_down_sync(0xffffffffu, v, 2);
    v += __shfl_down_sync(0xffffffffu, v, 1);
    return v;
}

// ---------------- SpMM1 over half g1 (bucket CSR) -> g_col only ----------------
__global__ void __launch_bounds__(256) k_spmm1(const float* __restrict__ b1,
                                               const float* __restrict__ W2) {
    int t = blockIdx.y;
    const __half* __restrict__ g = g_g1[t];

    __shared__ float w2c[H_];
    int tid = threadIdx.x;
    if (tid < H_) w2c[tid] = W2[(size_t)tid * H_ + (H_ - 1)];
    __syncthreads();

    int warp = tid >> 5, lane = tid & 31;
    int row = blockIdx.x * 8 + warp;
    if (row >= N_) return;

    int s0 = row * CAP_;
    int s1 = s0 + min(g_cnt[t][row], CAP_);
    const int* __restrict__ csr = g_bucket[t];
    int co = lane * 4;

    float ax = 0.f, ay = 0.f, az = 0.f, aw = 0.f;
    int j = s0;
    for (; j + 4 <= s1; j += 4) {
        int i0 = csr[j], i1 = csr[j + 1], i2 = csr[j + 2], i3 = csr[j + 3];
        uint2 r0 = *(const uint2*)&g[(size_t)i0 * H_ + co];
        uint2 r1 = *(const uint2*)&g[(size_t)i1 * H_ + co];
        uint2 r2 = *(const uint2*)&g[(size_t)i2 * H_ + co];
        uint2 r3 = *(const uint2*)&g[(size_t)i3 * H_ + co];
        float2 f;
        f = __half22float2(*(__half2*)&r0.x); ax += f.x; ay += f.y;
        f = __half22float2(*(__half2*)&r0.y); az += f.x; aw += f.y;
        f = __half22float2(*(__half2*)&r1.x); ax += f.x; ay += f.y;
        f = __half22float2(*(__half2*)&r1.y); az += f.x; aw += f.y;
        f = __half22float2(*(__half2*)&r2.x); ax += f.x; ay += f.y;
        f = __half22float2(*(__half2*)&r2.y); az += f.x; aw += f.y;
        f = __half22float2(*(__half2*)&r3.x); ax += f.x; ay += f.y;
        f = __half22float2(*(__half2*)&r3.y); az += f.x; aw += f.y;
    }
    for (; j < s1; j++) {
        uint2 r0 = *(const uint2*)&g[(size_t)csr[j] * H_ + co];
        float2 f;
        f = __half22float2(*(__half2*)&r0.x); ax += f.x; ay += f.y;
        f = __half22float2(*(__half2*)&r0.y); az += f.x; aw += f.y;
    }
    {
        uint2 r0 = *(const uint2*)&g[(size_t)row * H_ + co];
        float2 f;
        f = __half22float2(*(__half2*)&r0.x); ax += f.x; ay += f.y;
        f = __half22float2(*(__half2*)&r0.y); az += f.x; aw += f.y;
    }

    float d = g_dinv[t][row];
    float4 bb = *(const float4*)&b1[co];
    float h0 = fmaxf(fmaf(d, ax, bb.x), 0.f);
    float h1 = fmaxf(fmaf(d, ay, bb.y), 0.f);
    float h2 = fmaxf(fmaf(d, az, bb.z), 0.f);
    float h3 = fmaxf(fmaf(d, aw, bb.w), 0.f);

    float dot = h0 * w2c[co] + h1 * w2c[co + 1] + h2 * w2c[co + 2] + h3 * w2c[co + 3];
    dot = warp_sum(dot);
    if (lane == 0) g_col[t][row] = d * dot;
}

// ---------------- layer-2 scalar aggregation + fused argmax ----------------
__global__ void __launch_bounds__(256) k_col_argmax(const float* __restrict__ b2) {
    int t = blockIdx.y;
    int tid = threadIdx.x;
    int warp = tid >> 5, lane = tid & 31;
    int row = blockIdx.x * 8 + warp;
    unsigned long long p = 0ULL;
    float b = b2[H_ - 1];
    if (row < N_) {
        int s0 = row * CAP_;
        int s1 = s0 + min(g_cnt[t][row], CAP_);
        const int* __restrict__ csr = g_bucket[t];
        const float* __restrict__ col = g_col[t];
        float s = 0.f;
        for (int j = s0 + lane; j < s1; j += 32) s += col[csr[j]];
        s = warp_sum(s);
        if (lane == 0) {
            float d = g_dinv[t][row];
            if (d > 0.f) {
                float v = fmaxf(fmaf(d, s + col[row], b), 0.f);
                p = ((unsigned long long)__float_as_uint(v) << 32) |
                    (unsigned int)(0x7fffffff - row);
            }
        }
    }
    __shared__ unsigned long long sm[8];
    if (lane == 0) sm[warp] = p;
    __syncthreads();
    if (tid == 0) {
        unsigned long long m = sm[0];
#pragma unroll
        for (int i = 1; i < 8; i++) m = (sm[i] > m) ? sm[i] : m;
        if (m) atomicMax(&g_argmax[t], m);
    }
}

// ---------------- k_top: warp-per-neighbor recompute of h1; h2[top,:] -> g_seq ------
__global__ void __launch_bounds__(256) k_top(const float* __restrict__ b1,
                                             const float* __restrict__ W2,
                                             const float* __restrict__ b2) {
    int t = blockIdx.x;
    int top = 0x7fffffff - (int)(g_argmax[t] & 0x7fffffffULL);
    int tid = threadIdx.x;
    int warp = tid >> 5, lane = tid & 31;
    __shared__ float svec[H_];
    const __half* __restrict__ g = g_g1[t];
    const int* __restrict__ csr = g_bucket[t];

    if (tid < H_) svec[tid] = 0.f;
    __syncthreads();

    int s0 = top * CAP_;
    int deg = min(g_cnt[t][top], CAP_);
    int nU = 1 + deg;
    int co = lane * 4;

    for (int ui = warp; ui < nU; ui += 8) {
        int u = (ui == 0) ? top : csr[s0 + ui - 1];
        float du = g_dinv[t][u];
        if (du <= 0.f) continue;
        int u0 = u * CAP_;
        int u1 = u0 + min(g_cnt[t][u], CAP_);
        float ax = 0.f, ay = 0.f, az = 0.f, aw = 0.f;
        int j = u0;
        for (; j + 4 <= u1; j += 4) {
            uint2 r0 = *(const uint2*)&g[(size_t)csr[j] * H_ + co];
            uint2 r1 = *(const uint2*)&g[(size_t)csr[j + 1] * H_ + co];
            uint2 r2 = *(const uint2*)&g[(size_t)csr[j + 2] * H_ + co];
            uint2 r3 = *(const uint2*)&g[(size_t)csr[j + 3] * H_ + co];
            float2 f;
            f = __half22float2(*(__half2*)&r0.x); ax += f.x; ay += f.y;
            f = __half22float2(*(__half2*)&r0.y); az += f.x; aw += f.y;
            f = __half22float2(*(__half2*)&r1.x); ax += f.x; ay += f.y;
            f = __half22float2(*(__half2*)&r1.y); az += f.x; aw += f.y;
            f = __half22float2(*(__half2*)&r2.x); ax += f.x; ay += f.y;
            f = __half22float2(*(__half2*)&r2.y); az += f.x; aw += f.y;
            f = __half22float2(*(__half2*)&r3.x); ax += f.x; ay += f.y;
            f = __half22float2(*(__half2*)&r3.y); az += f.x; aw += f.y;
        }
        for (; j < u1; j++) {
            uint2 r0 = *(const uint2*)&g[(size_t)csr[j] * H_ + co];
            float2 f;
            f = __half22float2(*(__half2*)&r0.x); ax += f.x; ay += f.y;
            f = __half22float2(*(__half2*)&r0.y); az += f.x; aw += f.y;
        }
        {
            uint2 r0 = *(const uint2*)&g[(size_t)u * H_ + co];
            float2 f;
            f = __half22float2(*(__half2*)&r0.x); ax += f.x; ay += f.y;
            f = __half22float2(*(__half2*)&r0.y); az += f.x; aw += f.y;
        }
        float h0 = fmaxf(fmaf(du, ax, b1[co + 0]), 0.f);
        float h1 = fmaxf(fmaf(du, ay, b1[co + 1]), 0.f);
        float h2 = fmaxf(fmaf(du, az, b1[co + 2]), 0.f);
        float h3 = fmaxf(fmaf(du, aw, b1[co + 3]), 0.f);
        atomicAdd(&svec[co + 0], du * h0);
        atomicAdd(&svec[co + 1], du * h1);
        atomicAdd(&svec[co + 2], du * h2);
        atomicAdd(&svec[co + 3], du * h3);
    }
    __syncthreads();

    if (tid < H_) {
        float o = 0.f;
        int c = tid;
#pragma unroll 4
        for (int k = 0; k < H_; k++) o = fmaf(svec[k], W2[(size_t)k * H_ + c], o);
        float dtop = g_dinv[t][top];
        g_seq[t * H_ + c] = fmaxf(fmaf(dtop, o, b2[c]), 0.f);
    }
}

// ---------------- GRU input gates (parallel over t,o) ----------------
__global__ void __launch_bounds__(256) k_gi(const float* __restrict__ Wih,
                                            const float* __restrict__ bih) {
    int w = (blockIdx.x * 256 + threadIdx.x) >> 5;
    int lane = threadIdx.x & 31;
    if (w >= T_ * 3 * H_) return;
    int t = w / (3 * H_);
    int o = w - t * (3 * H_);
    float4 xv = *(const float4*)&g_seq[t * H_ + lane * 4];
    float4 wv = *(const float4*)&Wih[(size_t)o * H_ + lane * 4];
    float s = xv.x * wv.x + xv.y * wv.y + xv.z * wv.z + xv.w * wv.w;
    s = warp_sum(s);
    if (lane == 0) g_gi[t][o] = s + bih[o];
}

// ---------------- GRU recurrence + MLP head; Whh^T cached in smem ----------------
__global__ void __launch_bounds__(384) k_gru(const float* __restrict__ Whh,
                                             const float* __restrict__ bhh,
                                             const float* __restrict__ Wc1,
                                             const float* __restrict__ bc1,
                                             const float* __restrict__ Wc2,
                                             const float* __restrict__ bc2,
                                             float* __restrict__ out) {
    extern __shared__ float sW[];
    __shared__ float sh[H_], sgh[3 * H_], shid[H_ / 2];
    int tid = threadIdx.x;

    for (int e = tid * 4; e < 3 * H_ * H_; e += 384 * 4) {
        float4 v = *(const float4*)&Whh[e];
        int o = e >> 7;
        int k = e & 127;
        sW[(k + 0) * 385 + o] = v.x;
        sW[(k + 1) * 385 + o] = v.y;
        sW[(k + 2) * 385 + o] = v.z;
        sW[(k + 3) * 385 + o] = v.w;
    }
    if (tid < H_) sh[tid] = 0.f;
    float mybhh = bhh[tid];
    __syncthreads();

    for (int t = 0; t < T_; t++) {
        float acc = mybhh;
#pragma unroll 8
        for (int k = 0; k < H_; k++) acc = fmaf(sh[k], sW[k * 385 + tid], acc);
        sgh[tid] = acc;
        __syncthreads();
        float hn = 0.f;
        if (tid < H_) {
            float r = 1.0f / (1.0f + expf(-(g_gi[t][tid] + sgh[tid])));
            float z = 1.0f / (1.0f + expf(-(g_gi[t][tid + H_] + sgh[tid + H_])));
            float n = tanhf(g_gi[t][tid + 2 * H_] + r * sgh[tid + 2 * H_]);
            hn = (1.0f - z) * n + z * sh[tid];
        }
        __syncthreads();
        if (tid < H_) sh[tid] = hn;
        __syncthreads();
    }

    if (tid < H_ / 2) {
        float s = bc1[tid];
        for (int k = 0; k < H_; k++) s += sh[k] * Wc1[(size_t)k * (H_ / 2) + tid];
        shid[tid] = fmaxf(s, 0.0f);
    }
    __syncthreads();
    if (tid == 0) {
        float s = bc2[0];
        for (int j = 0; j < H_ / 2; j++) s += shid[j] * Wc2[j];
        out[0] = 1.0f / (1.0f + expf(-s));
    }
}

// ---------------- launch ----------------
extern "C" void kernel_launch(void* const* d_in, const int* in_sizes, int n_in,
                              void* d_out, int out_size) {
    const float* x   = (const float*)d_in[0];
    const int*   ei  = (const int*)d_in[1];
    const int*   tgt = (const int*)d_in[2];
    const float* W1  = (const float*)d_in[3];
    const float* b1  = (const float*)d_in[4];
    const float* W2  = (const float*)d_in[5];
    const float* b2  = (const float*)d_in[6];
    const float* Wih = (const float*)d_in[7];
    const float* Whh = (const float*)d_in[8];
    const float* bih = (const float*)d_in[9];
    const float* bhh = (const float*)d_in[10];
    const float* Wc1 = (const float*)d_in[11];
    const float* bc1 = (const float*)d_in[12];
    const float* Wc2 = (const float*)d_in[13];
    const float* bc2 = (const float*)d_in[14];
    float* out = (float*)d_out;

    const dim3 GRST((N_ / 4 + 255) / 256, T_);
    const dim3 GN((N_ + 255) / 256, T_);
    const dim3 GE((E_ + 255) / 256, T_);
    const dim3 GM((N_ + BM2 - 1) / BM2, T_);
    const dim3 GR((N_ + 7) / 8, T_);
    const dim3 GX((N_ * F_ / 4 + 255) / 256, T_);
    const int GI_BLOCKS = (T_ * 3 * H_ * 32 + 255) / 256;

    const int GEMM_SMEM = BM2 * A_LDM * 2 + F_ * H_ * 2;
    const int GRU_SMEM = H_ * 385 * (int)sizeof(float);
    static int smem_set = 0;
    if (!smem_set) {
        cudaFuncSetAttribute(k_gemm, cudaFuncAttributeMaxDynamicSharedMemorySize, GEMM_SMEM);
        cudaFuncSetAttribute(k_gru, cudaFuncAttributeMaxDynamicSharedMemorySize, GRU_SMEM);
        smem_set = 1;
    }

    cudaStream_t s2;
    cudaStreamCreateWithFlags(&s2, cudaStreamNonBlocking);
    cudaEvent_t evF, evX, evJ;
    cudaEventCreateWithFlags(&evF, cudaEventDisableTiming);
    cudaEventCreateWithFlags(&evX, cudaEventDisableTiming);
    cudaEventCreateWithFlags(&evJ, cudaEventDisableTiming);

    k_init<<<GRST, 256>>>(tgt);   // seeds lvl, zeroes cnt/sdeg/argmax

    // fork: side stream: half conversions then bucket-CSR fill
    cudaEventRecord(evF, cudaStreamPerThread);
    cudaStreamWaitEvent(s2, evF, 0);
    k_xhalf<<<GX, 256, 0, s2>>>(x);
    k_w1half<<<1, 256, 0, s2>>>(W1);
    cudaEventRecord(evX, s2);               // xh ready
    k_fill<<<GE, 256, 0, s2>>>(ei);
    cudaEventRecord(evJ, s2);               // CSR ready

    // main stream: BFS then edge-centric degree + dinv
    k_prop<<<GE, 256>>>(ei, 1);
    k_prop<<<GE, 256>>>(ei, 2);
    k_edeg<<<GE, 256>>>(ei);
    k_dinv<<<GN, 256>>>();

    // gemm needs xh + dinv (not CSR)
    cudaStreamWaitEvent(cudaStreamPerThread, evX, 0);
    k_gemm<<<GM, 256, GEMM_SMEM>>>(W1);

    // spmm needs CSR too
    cudaStreamWaitEvent(cudaStreamPerThread, evJ, 0);
    k_spmm1<<<GR, 256>>>(b1, W2);
    k_col_argmax<<<GR, 256>>>(b2);
    k_top<<<T_, 256>>>(b1, W2, b2);
    k_gi<<<GI_BLOCKS, 256>>>(Wih, bih);
    k_gru<<<1, 384, GRU_SMEM>>>(Whh, bhh, Wc1, bc1, Wc2, bc2, out);

    cudaStreamCaptureStatus cs = cudaStreamCaptureStatusNone;
    cudaStreamIsCapturing(cudaStreamPerThread, &cs);
    cudaEventDestroy(evF);
    cudaEventDestroy(evX);
    cudaEventDestroy(evJ);
    if (cs == cudaStreamCaptureStatusNone) cudaStreamDestroy(s2);
}